// round 7
// baseline (speedup 1.0000x reference)
#include <cuda_runtime.h>
#include <cuda_bf16.h>
#include <cstdint>

#define NIN 128
#define TM  64

// ---- SMEM map (bytes), per CTA (fits 2 CTAs/SM) ----
// A tiles: 16x16 bf16 tiles, 512B each, XOR-swizzled rows.
//   GEMM1 (inter): tile index = mt*8 + kc   (32 tiles, 16KB used per hi/lo)
//   GEMM2 (h)    : tile index = mt*16 + kc  (64 tiles, 32KB per hi/lo)
#define OFF_AHI 0
#define OFF_ALO 32768
#define OFF_BAS 65536                 // 64 * 17 * 4 = 4352
#define OFF_OUT 69888                 // 64 * 132 * 4 = 33792
#define SMEM_BYTES 103680

// ---- device scratch: fragment-ordered bf16x2-split weights ----
__device__ __align__(16) unsigned g_W1v_hi[16384];
__device__ __align__(16) unsigned g_W1v_lo[16384];
__device__ __align__(16) unsigned g_W2v_hi[262144];
__device__ __align__(16) unsigned g_W2v_lo[262144];
__device__ int g_idx64;

// -------- helpers --------
__device__ __forceinline__ uint32_t smem_u32(const void* p) {
    uint32_t a;
    asm("{ .reg .u64 t; cvta.to.shared.u64 t, %1; cvt.u32.u64 %0, t; }" : "=r"(a) : "l"(p));
    return a;
}
__device__ __forceinline__ unsigned pk(float x0, float x1, unsigned& lo) {
    __nv_bfloat16 h0 = __float2bfloat16(x0), h1 = __float2bfloat16(x1);
    float r0 = x0 - __bfloat162float(h0);
    float r1 = x1 - __bfloat162float(h1);
    __nv_bfloat16 l0 = __float2bfloat16(r0), l1 = __float2bfloat16(r1);
    lo = ((unsigned)__bfloat16_as_ushort(l1) << 16) | (unsigned)__bfloat16_as_ushort(l0);
    return ((unsigned)__bfloat16_as_ushort(h1) << 16) | (unsigned)__bfloat16_as_ushort(h0);
}
__device__ __forceinline__ void st128s(uint32_t a, unsigned x, unsigned y, unsigned z, unsigned w) {
    asm volatile("st.shared.v4.b32 [%0], {%1,%2,%3,%4};" :: "r"(a), "r"(x), "r"(y), "r"(z), "r"(w) : "memory");
}
__device__ __forceinline__ void sts32(uint32_t a, unsigned v) {
    asm volatile("st.shared.b32 [%0], %1;" :: "r"(a), "r"(v) : "memory");
}
__device__ __forceinline__ void ldm4(unsigned (&a)[4], uint32_t addr) {
    asm volatile("ldmatrix.sync.aligned.m8n8.x4.shared.b16 {%0,%1,%2,%3}, [%4];"
                 : "=r"(a[0]), "=r"(a[1]), "=r"(a[2]), "=r"(a[3]) : "r"(addr));
}
__device__ __forceinline__ void mma4(float (&d)[4], const unsigned (&a)[4], unsigned b0, unsigned b1) {
    asm volatile(
        "mma.sync.aligned.m16n8k16.row.col.f32.bf16.bf16.f32 "
        "{%0,%1,%2,%3},{%4,%5,%6,%7},{%8,%9},{%0,%1,%2,%3};\n"
        : "+f"(d[0]), "+f"(d[1]), "+f"(d[2]), "+f"(d[3])
        : "r"(a[0]), "r"(a[1]), "r"(a[2]), "r"(a[3]), "r"(b0), "r"(b1));
}

// -------- prep kernels --------
__global__ void detect_idx_kernel(const unsigned* __restrict__ idx_raw) {
    if (threadIdx.x == 0) {
        unsigned nz = 0;
        #pragma unroll 1
        for (int k = 0; k < 64; k++) nz |= idx_raw[2 * k + 1];
        g_idx64 = (nz == 0) ? 1 : 0;  // int64 values < 2^31 -> high words all zero
    }
}

// W1 [128,256] -> per-(ks,w,lane) 8-word fragments (nt=4 across 32 cols/warp)
__global__ void prep_w1_kernel(const float* __restrict__ W1) {
    int i = blockIdx.x * 256 + threadIdx.x;        // 16384
    int e = i & 7, lane = (i >> 3) & 31, w = (i >> 8) & 7, ks = i >> 11;
    int q = lane & 3, r = lane >> 2;
    int kpair = ks * 8 + (e & 1) * 4 + q;
    int col = w * 32 + r + (e >> 1) * 8;
    float x0 = W1[(2 * kpair) * 256 + col];
    float x1 = W1[(2 * kpair + 1) * 256 + col];
    unsigned lo, hi = pk(x0, x1, lo);
    g_W1v_hi[i] = hi; g_W1v_lo[i] = lo;
}

// W2 [256,2048] -> per-(t,w,lane) 4-word fragments (nt=2 across 16 cols/warp)
// t = pass*16 + ks, pass in [0,16), ks in [0,16)
__global__ void prep_w2_kernel(const float* __restrict__ W2) {
    int i = blockIdx.x * 256 + threadIdx.x;        // 262144
    int e = i & 3, lane = (i >> 2) & 31, w = (i >> 7) & 7, t = i >> 10;
    int ks = t & 15, pass = t >> 4;
    int q = lane & 3, r = lane >> 2;
    int kpair = ks * 8 + (e & 1) * 4 + q;
    int col = pass * 128 + w * 16 + r + (e >> 1) * 8;
    float x0 = W2[(2 * kpair) * 2048 + col];
    float x1 = W2[(2 * kpair + 1) * 2048 + col];
    unsigned lo, hi = pk(x0, x1, lo);
    g_W2v_hi[i] = hi; g_W2v_lo[i] = lo;
}

// -------- main fused kernel: one CTA per 64-edge tile, 2 CTAs/SM --------
__global__ void __launch_bounds__(256, 2) pilayer_kernel(
    const float* __restrict__ prop, const void* __restrict__ idxi_raw,
    const void* __restrict__ idxj_raw, const float* __restrict__ basis,
    float* __restrict__ out, int P)
{
    extern __shared__ __align__(1024) char smem[];
    const uint32_t su = smem_u32(smem);
    float* sBas = (float*)(smem + OFF_BAS);
    float* sOut = (float*)(smem + OFF_OUT);

    const int tid = threadIdx.x;
    const int w = tid >> 5, lane = tid & 31, q = lane & 3, r = lane >> 2;
    const int m0 = blockIdx.x * TM;
    const int mvalid = min(TM, P - m0);
    const bool is64 = (g_idx64 != 0);

    // per-lane ldmatrix offset within a 512B 16x16 tile
    const int rL = (lane & 7) + (lane & 8);
    const int hL = lane >> 4;
    const uint32_t lmoff = (uint32_t)((rL * 32 + hL * 16) ^ ((rL & 4) << 2));
    const uint32_t aHiB = su + OFF_AHI + lmoff;
    const uint32_t aLoB = su + OFF_ALO + lmoff;

    // ---- gather: inter = prop[idx_i] + prop[idx_j]; bf16 hi/lo split, swizzled tiles ----
    {
        const int m = tid >> 2, qtr = tid & 3;     // 4 threads per row, 32 k-cols each
        const int mt = m >> 4, rr = m & 15;
        const unsigned swz = (unsigned)((rr & 4) << 2);
        const uint32_t o0 = (uint32_t)((rr * 32) ^ swz);
        const uint32_t o1 = o0 ^ 16u;
        if (m < mvalid) {
            long long e = (long long)(m0 + m);
            long long ia, ja;
            if (is64) { ia = ((const long long*)idxi_raw)[e]; ja = ((const long long*)idxj_raw)[e]; }
            else      { ia = ((const int*)idxi_raw)[e];       ja = ((const int*)idxj_raw)[e]; }
            const float4* pi = (const float4*)(prop + ia * NIN);
            const float4* pj = (const float4*)(prop + ja * NIN);
            #pragma unroll
            for (int kc = 0; kc < 2; kc++) {
                const int kcg = qtr * 2 + kc;
                const uint32_t tb = (uint32_t)((mt * 8 + kcg) * 512);
                float4 A0 = pi[kcg * 4], A1 = pi[kcg * 4 + 1], A2 = pi[kcg * 4 + 2], A3 = pi[kcg * 4 + 3];
                float4 B0 = pj[kcg * 4], B1 = pj[kcg * 4 + 1], B2 = pj[kcg * 4 + 2], B3 = pj[kcg * 4 + 3];
                unsigned h0, h1, h2, h3, h4, h5, h6, h7, l0, l1, l2, l3, l4, l5, l6, l7;
                h0 = pk(A0.x + B0.x, A0.y + B0.y, l0);
                h1 = pk(A0.z + B0.z, A0.w + B0.w, l1);
                h2 = pk(A1.x + B1.x, A1.y + B1.y, l2);
                h3 = pk(A1.z + B1.z, A1.w + B1.w, l3);
                h4 = pk(A2.x + B2.x, A2.y + B2.y, l4);
                h5 = pk(A2.z + B2.z, A2.w + B2.w, l5);
                h6 = pk(A3.x + B3.x, A3.y + B3.y, l6);
                h7 = pk(A3.z + B3.z, A3.w + B3.w, l7);
                st128s(su + OFF_AHI + tb + o0, h0, h1, h2, h3);
                st128s(su + OFF_AHI + tb + o1, h4, h5, h6, h7);
                st128s(su + OFF_ALO + tb + o0, l0, l1, l2, l3);
                st128s(su + OFF_ALO + tb + o1, l4, l5, l6, l7);
            }
        } else {
            #pragma unroll
            for (int kc = 0; kc < 2; kc++) {
                const uint32_t tb = (uint32_t)((mt * 8 + qtr * 2 + kc) * 512);
                st128s(su + OFF_AHI + tb + o0, 0, 0, 0, 0);
                st128s(su + OFF_AHI + tb + o1, 0, 0, 0, 0);
                st128s(su + OFF_ALO + tb + o0, 0, 0, 0, 0);
                st128s(su + OFF_ALO + tb + o1, 0, 0, 0, 0);
            }
        }
        // basis rows (zero-padded past mvalid): each thread one float4
        float4 b0;
        if (m < mvalid) b0 = ((const float4*)(basis + (size_t)(m0 + m) * 16))[qtr];
        else            b0 = make_float4(0.f, 0.f, 0.f, 0.f);
        float* bd = sBas + m * 17 + qtr * 4;
        bd[0] = b0.x; bd[1] = b0.y; bd[2] = b0.z; bd[3] = b0.w;
    }
    __syncthreads();

    const unsigned* pW1h = g_W1v_hi + (w * 32 + lane) * 8;
    const unsigned* pW1l = g_W1v_lo + (w * 32 + lane) * 8;
    const unsigned* pW2h = g_W2v_hi + (w * 32 + lane) * 4;
    const unsigned* pW2l = g_W2v_lo + (w * 32 + lane) * 4;

    // ================= GEMM1: pre = inter @ W1 (M=64, N=256, K=128), bf16x3 =================
    {
        float acc[4][4][4];
        #pragma unroll
        for (int mt = 0; mt < 4; mt++)
            #pragma unroll
            for (int nt = 0; nt < 4; nt++)
                #pragma unroll
                for (int e = 0; e < 4; e++) acc[mt][nt][e] = 0.f;

        uint4 bh0 = *(const uint4*)(pW1h), bh1 = *(const uint4*)(pW1h + 4);
        uint4 bl0 = *(const uint4*)(pW1l), bl1 = *(const uint4*)(pW1l + 4);

        #pragma unroll 1
        for (int ks = 0; ks < 8; ks++) {
            const int ksn = (ks < 7) ? (ks + 1) : 0;
            const unsigned* nh = pW1h + ksn * 2048;
            const unsigned* nl = pW1l + ksn * 2048;
            uint4 nh0 = *(const uint4*)(nh), nh1 = *(const uint4*)(nh + 4);
            uint4 nl0 = *(const uint4*)(nl), nl1 = *(const uint4*)(nl + 4);
            const unsigned Bh[4][2] = {{bh0.x, bh0.y}, {bh0.z, bh0.w}, {bh1.x, bh1.y}, {bh1.z, bh1.w}};
            const unsigned Bl[4][2] = {{bl0.x, bl0.y}, {bl0.z, bl0.w}, {bl1.x, bl1.y}, {bl1.z, bl1.w}};
            #pragma unroll
            for (int mt = 0; mt < 4; mt++) {
                unsigned ahi[4], alo[4];
                ldm4(ahi, aHiB + (uint32_t)((mt * 8 + ks) * 512));
                ldm4(alo, aLoB + (uint32_t)((mt * 8 + ks) * 512));
                #pragma unroll
                for (int nt = 0; nt < 4; nt++) {
                    mma4(acc[mt][nt], ahi, Bh[nt][0], Bh[nt][1]);
                    mma4(acc[mt][nt], ahi, Bl[nt][0], Bl[nt][1]);
                    mma4(acc[mt][nt], alo, Bh[nt][0], Bh[nt][1]);
                }
            }
            bh0 = nh0; bh1 = nh1; bl0 = nl0; bl1 = nl1;
        }
        __syncthreads();  // all inter reads complete before h overwrites the tile region

        // ---- tanh + split + store h tiles ----
        #pragma unroll
        for (int mt = 0; mt < 4; mt++) {
            #pragma unroll
            for (int nt = 0; nt < 4; nt++) {
                const int e = nt & 1;
                const uint32_t tb = (uint32_t)((mt * 16 + 2 * w + (nt >> 1)) * 512);
                const int inrow = 16 * e + 4 * q;
                unsigned lo;
                unsigned hi = pk(tanhf(acc[mt][nt][0]), tanhf(acc[mt][nt][1]), lo);
                uint32_t o = (uint32_t)((r * 32 + inrow) ^ ((r & 4) << 2));
                sts32(su + OFF_AHI + tb + o, hi);
                sts32(su + OFF_ALO + tb + o, lo);
                hi = pk(tanhf(acc[mt][nt][2]), tanhf(acc[mt][nt][3]), lo);
                const int r1 = r + 8;
                o = (uint32_t)((r1 * 32 + inrow) ^ ((r1 & 4) << 2));
                sts32(su + OFF_AHI + tb + o, hi);
                sts32(su + OFF_ALO + tb + o, lo);
            }
        }
    }
    __syncthreads();

    // ================= GEMM2: H = tanh @ W2 (M=64, N=2048, K=256) + basis epilogue ========
    // Flattened: 256 t-steps (pass = t>>4, kc = t&15), epilogue every 16 steps.
    {
        float acc[4][2][4];
        #pragma unroll
        for (int mt = 0; mt < 4; mt++)
            #pragma unroll
            for (int nt = 0; nt < 2; nt++)
                #pragma unroll
                for (int e = 0; e < 4; e++) acc[mt][nt][e] = 0.f;

        uint4 bh = *(const uint4*)(pW2h);
        uint4 bl = *(const uint4*)(pW2l);

        #pragma unroll 1
        for (int t = 0; t < 256; t++) {
            const int tn = (t < 255) ? (t + 1) : 0;
            uint4 nh = *(const uint4*)(pW2h + tn * 1024);
            uint4 nl = *(const uint4*)(pW2l + tn * 1024);
            const int kc = t & 15;
            #pragma unroll
            for (int mt = 0; mt < 4; mt++) {
                unsigned ahi[4], alo[4];
                ldm4(ahi, aHiB + (uint32_t)((mt * 16 + kc) * 512));
                ldm4(alo, aLoB + (uint32_t)((mt * 16 + kc) * 512));
                mma4(acc[mt][0], ahi, bh.x, bh.y);
                mma4(acc[mt][0], ahi, bl.x, bl.y);
                mma4(acc[mt][0], alo, bh.x, bh.y);
                mma4(acc[mt][1], ahi, bh.z, bh.w);
                mma4(acc[mt][1], ahi, bl.z, bl.w);
                mma4(acc[mt][1], alo, bh.z, bh.w);
            }
            bh = nh; bl = nl;

            if (kc == 15) {
                const int pass = t >> 4;
                const int c = pass * 8 + w;   // this warp's output column
                #pragma unroll
                for (int mt = 0; mt < 4; mt++) {
                    const int row0 = mt * 16 + r, row1 = row0 + 8;
                    float b00 = sBas[row0 * 17 + 2 * q],     b01 = sBas[row0 * 17 + 2 * q + 1];
                    float b08 = sBas[row0 * 17 + 8 + 2 * q], b09 = sBas[row0 * 17 + 9 + 2 * q];
                    float b10 = sBas[row1 * 17 + 2 * q],     b11 = sBas[row1 * 17 + 2 * q + 1];
                    float b18 = sBas[row1 * 17 + 8 + 2 * q], b19 = sBas[row1 * 17 + 9 + 2 * q];
                    float s0 = acc[mt][0][0] * b00 + acc[mt][0][1] * b01
                             + acc[mt][1][0] * b08 + acc[mt][1][1] * b09;
                    float s1 = acc[mt][0][2] * b10 + acc[mt][0][3] * b11
                             + acc[mt][1][2] * b18 + acc[mt][1][3] * b19;
                    s0 += __shfl_xor_sync(0xffffffffu, s0, 1);
                    s0 += __shfl_xor_sync(0xffffffffu, s0, 2);
                    s1 += __shfl_xor_sync(0xffffffffu, s1, 1);
                    s1 += __shfl_xor_sync(0xffffffffu, s1, 2);
                    if (q == 0) {
                        sOut[row0 * 132 + c] = s0;
                        sOut[row1 * 132 + c] = s1;
                    }
                    #pragma unroll
                    for (int nt = 0; nt < 2; nt++)
                        #pragma unroll
                        for (int e = 0; e < 4; e++) acc[mt][nt][e] = 0.f;
                }
            }
        }
    }
    __syncthreads();

    // ---- coalesced output store ----
    #pragma unroll 1
    for (int i = tid; i < TM * 32; i += 256) {
        const int m = i >> 5, c4 = i & 31;
        if (m < mvalid) {
            const float4 v = *(const float4*)(sOut + m * 132 + c4 * 4);
            *(float4*)(out + ((size_t)(m0 + m)) * NIN + c4 * 4) = v;
        }
    }
}

extern "C" void kernel_launch(void* const* d_in, const int* in_sizes, int n_in,
                              void* d_out, int out_size) {
    const float* prop  = (const float*)d_in[0];
    const void*  idxi  = d_in[1];
    const void*  idxj  = d_in[2];
    const float* basis = (const float*)d_in[3];
    const float* W1    = (const float*)d_in[4];
    const float* W2    = (const float*)d_in[5];
    float* out = (float*)d_out;
    const int P = out_size / NIN;
    (void)in_sizes; (void)n_in;

    cudaFuncSetAttribute(pilayer_kernel, cudaFuncAttributeMaxDynamicSharedMemorySize, SMEM_BYTES);

    detect_idx_kernel<<<1, 32>>>((const unsigned*)idxi);
    prep_w1_kernel<<<64, 256>>>(W1);
    prep_w2_kernel<<<1024, 256>>>(W2);

    const int blocks = (P + TM - 1) / TM;
    pilayer_kernel<<<blocks, 256, SMEM_BYTES>>>(prop, idxi, idxj, basis, out, P);
}

// round 8
// speedup vs baseline: 1.3853x; 1.3853x over previous
#include <cuda_runtime.h>
#include <cuda_bf16.h>
#include <cstdint>

#define NIN 128
#define TM  64

// ---- SMEM map (bytes), per CTA (fits 2 CTAs/SM) ----
// A tiles: 16x16 bf16 tiles, 512B each, XOR-swizzled rows.
//   GEMM1 (inter): tile index = mt*8 + kc   (32 tiles, 16KB per hi/lo)
//   GEMM2 (h)    : tile index = mt*16 + kc  (64 tiles, 32KB per hi/lo)
#define OFF_AHI 0
#define OFF_ALO 32768
#define OFF_BAS 65536                 // 64 * 17 * 4 = 4352
#define OFF_OUT 69888                 // 64 * 132 * 4 = 33792
#define SMEM_BYTES 103680

// ---- device scratch: fragment-ordered bf16x2-split weights ----
__device__ __align__(16) unsigned g_W1v_hi[16384];
__device__ __align__(16) unsigned g_W1v_lo[16384];
__device__ __align__(16) unsigned g_W2v_hi[262144];
__device__ __align__(16) unsigned g_W2v_lo[262144];
__device__ int g_idx64;

// -------- helpers --------
__device__ __forceinline__ uint32_t smem_u32(const void* p) {
    uint32_t a;
    asm("{ .reg .u64 t; cvta.to.shared.u64 t, %1; cvt.u32.u64 %0, t; }" : "=r"(a) : "l"(p));
    return a;
}
__device__ __forceinline__ unsigned pk(float x0, float x1, unsigned& lo) {
    __nv_bfloat16 h0 = __float2bfloat16(x0), h1 = __float2bfloat16(x1);
    float r0 = x0 - __bfloat162float(h0);
    float r1 = x1 - __bfloat162float(h1);
    __nv_bfloat16 l0 = __float2bfloat16(r0), l1 = __float2bfloat16(r1);
    lo = ((unsigned)__bfloat16_as_ushort(l1) << 16) | (unsigned)__bfloat16_as_ushort(l0);
    return ((unsigned)__bfloat16_as_ushort(h1) << 16) | (unsigned)__bfloat16_as_ushort(h0);
}
__device__ __forceinline__ void st128s(uint32_t a, unsigned x, unsigned y, unsigned z, unsigned w) {
    asm volatile("st.shared.v4.b32 [%0], {%1,%2,%3,%4};" :: "r"(a), "r"(x), "r"(y), "r"(z), "r"(w) : "memory");
}
__device__ __forceinline__ void sts32(uint32_t a, unsigned v) {
    asm volatile("st.shared.b32 [%0], %1;" :: "r"(a), "r"(v) : "memory");
}
__device__ __forceinline__ void ldm4(unsigned (&a)[4], uint32_t addr) {
    asm volatile("ldmatrix.sync.aligned.m8n8.x4.shared.b16 {%0,%1,%2,%3}, [%4];"
                 : "=r"(a[0]), "=r"(a[1]), "=r"(a[2]), "=r"(a[3]) : "r"(addr));
}
__device__ __forceinline__ void mma4(float (&d)[4], const unsigned (&a)[4], unsigned b0, unsigned b1) {
    asm volatile(
        "mma.sync.aligned.m16n8k16.row.col.f32.bf16.bf16.f32 "
        "{%0,%1,%2,%3},{%4,%5,%6,%7},{%8,%9},{%0,%1,%2,%3};\n"
        : "+f"(d[0]), "+f"(d[1]), "+f"(d[2]), "+f"(d[3])
        : "r"(a[0]), "r"(a[1]), "r"(a[2]), "r"(a[3]), "r"(b0), "r"(b1));
}

// -------- prep kernels --------
__global__ void detect_idx_kernel(const unsigned* __restrict__ idx_raw) {
    if (threadIdx.x == 0) {
        unsigned nz = 0;
        #pragma unroll 1
        for (int k = 0; k < 64; k++) nz |= idx_raw[2 * k + 1];
        g_idx64 = (nz == 0) ? 1 : 0;  // int64 values < 2^31 -> high words all zero
    }
}

// W1 [128,256] -> per-(ks,w,lane) 8-word fragments (nt=4 across 32 cols/warp)
__global__ void prep_w1_kernel(const float* __restrict__ W1) {
    int i = blockIdx.x * 256 + threadIdx.x;        // 16384
    int e = i & 7, lane = (i >> 3) & 31, w = (i >> 8) & 7, ks = i >> 11;
    int q = lane & 3, r = lane >> 2;
    int kpair = ks * 8 + (e & 1) * 4 + q;
    int col = w * 32 + r + (e >> 1) * 8;
    float x0 = W1[(2 * kpair) * 256 + col];
    float x1 = W1[(2 * kpair + 1) * 256 + col];
    unsigned lo, hi = pk(x0, x1, lo);
    g_W1v_hi[i] = hi; g_W1v_lo[i] = lo;
}

// W2 [256,2048] -> per-(pass,ks,w,lane) 8-word fragments (nt=4 across 32 cols/warp)
__global__ void prep_w2_kernel(const float* __restrict__ W2) {
    int i = blockIdx.x * 256 + threadIdx.x;        // 262144
    int e = i & 7, lane = (i >> 3) & 31, w = (i >> 8) & 7;
    int ks = (i >> 11) & 15, pass = i >> 15;
    int q = lane & 3, r = lane >> 2;
    int kpair = ks * 8 + (e & 1) * 4 + q;
    int col = pass * 256 + w * 32 + r + (e >> 1) * 8;
    float x0 = W2[(2 * kpair) * 2048 + col];
    float x1 = W2[(2 * kpair + 1) * 2048 + col];
    unsigned lo, hi = pk(x0, x1, lo);
    g_W2v_hi[i] = hi; g_W2v_lo[i] = lo;
}

// -------- main fused kernel: one CTA per 64-edge tile, 2 CTAs/SM, N=32 cols/warp --------
__global__ void __launch_bounds__(256, 2) pilayer_kernel(
    const float* __restrict__ prop, const void* __restrict__ idxi_raw,
    const void* __restrict__ idxj_raw, const float* __restrict__ basis,
    float* __restrict__ out, int P)
{
    extern __shared__ __align__(1024) char smem[];
    const uint32_t su = smem_u32(smem);
    float* sBas = (float*)(smem + OFF_BAS);
    float* sOut = (float*)(smem + OFF_OUT);

    const int tid = threadIdx.x;
    const int w = tid >> 5, lane = tid & 31, q = lane & 3, r = lane >> 2;
    const int m0 = blockIdx.x * TM;
    const int mvalid = min(TM, P - m0);
    const bool is64 = (g_idx64 != 0);

    // per-lane ldmatrix offset within a 512B 16x16 tile
    const int rL = (lane & 7) + (lane & 8);
    const int hL = lane >> 4;
    const uint32_t lmoff = (uint32_t)((rL * 32 + hL * 16) ^ ((rL & 4) << 2));
    const uint32_t aHiB = su + OFF_AHI + lmoff;
    const uint32_t aLoB = su + OFF_ALO + lmoff;

    // ---- gather: inter = prop[idx_i] + prop[idx_j]; bf16 hi/lo split, swizzled tiles ----
    {
        const int m = tid >> 2, qtr = tid & 3;     // 4 threads per row, 32 k-cols each
        const int mt = m >> 4, rr = m & 15;
        const unsigned swz = (unsigned)((rr & 4) << 2);
        const uint32_t o0 = (uint32_t)((rr * 32) ^ swz);
        const uint32_t o1 = o0 ^ 16u;
        if (m < mvalid) {
            long long e = (long long)(m0 + m);
            long long ia, ja;
            if (is64) { ia = ((const long long*)idxi_raw)[e]; ja = ((const long long*)idxj_raw)[e]; }
            else      { ia = ((const int*)idxi_raw)[e];       ja = ((const int*)idxj_raw)[e]; }
            const float4* pi = (const float4*)(prop + ia * NIN);
            const float4* pj = (const float4*)(prop + ja * NIN);
            #pragma unroll
            for (int kc = 0; kc < 2; kc++) {
                const int kcg = qtr * 2 + kc;
                const uint32_t tb = (uint32_t)((mt * 8 + kcg) * 512);
                float4 A0 = pi[kcg * 4], A1 = pi[kcg * 4 + 1], A2 = pi[kcg * 4 + 2], A3 = pi[kcg * 4 + 3];
                float4 B0 = pj[kcg * 4], B1 = pj[kcg * 4 + 1], B2 = pj[kcg * 4 + 2], B3 = pj[kcg * 4 + 3];
                unsigned h0, h1, h2, h3, h4, h5, h6, h7, l0, l1, l2, l3, l4, l5, l6, l7;
                h0 = pk(A0.x + B0.x, A0.y + B0.y, l0);
                h1 = pk(A0.z + B0.z, A0.w + B0.w, l1);
                h2 = pk(A1.x + B1.x, A1.y + B1.y, l2);
                h3 = pk(A1.z + B1.z, A1.w + B1.w, l3);
                h4 = pk(A2.x + B2.x, A2.y + B2.y, l4);
                h5 = pk(A2.z + B2.z, A2.w + B2.w, l5);
                h6 = pk(A3.x + B3.x, A3.y + B3.y, l6);
                h7 = pk(A3.z + B3.z, A3.w + B3.w, l7);
                st128s(su + OFF_AHI + tb + o0, h0, h1, h2, h3);
                st128s(su + OFF_AHI + tb + o1, h4, h5, h6, h7);
                st128s(su + OFF_ALO + tb + o0, l0, l1, l2, l3);
                st128s(su + OFF_ALO + tb + o1, l4, l5, l6, l7);
            }
        } else {
            #pragma unroll
            for (int kc = 0; kc < 2; kc++) {
                const uint32_t tb = (uint32_t)((mt * 8 + qtr * 2 + kc) * 512);
                st128s(su + OFF_AHI + tb + o0, 0, 0, 0, 0);
                st128s(su + OFF_AHI + tb + o1, 0, 0, 0, 0);
                st128s(su + OFF_ALO + tb + o0, 0, 0, 0, 0);
                st128s(su + OFF_ALO + tb + o1, 0, 0, 0, 0);
            }
        }
        // basis rows (zero-padded past mvalid): each thread one float4
        float4 b0;
        if (m < mvalid) b0 = ((const float4*)(basis + (size_t)(m0 + m) * 16))[qtr];
        else            b0 = make_float4(0.f, 0.f, 0.f, 0.f);
        float* bd = sBas + m * 17 + qtr * 4;
        bd[0] = b0.x; bd[1] = b0.y; bd[2] = b0.z; bd[3] = b0.w;
    }
    __syncthreads();

    const unsigned* pW1h = g_W1v_hi + (w * 32 + lane) * 8;
    const unsigned* pW1l = g_W1v_lo + (w * 32 + lane) * 8;
    const unsigned* pW2h = g_W2v_hi + (w * 32 + lane) * 8;
    const unsigned* pW2l = g_W2v_lo + (w * 32 + lane) * 8;

    float acc[4][4][4];
    #pragma unroll
    for (int mt = 0; mt < 4; mt++)
        #pragma unroll
        for (int nt = 0; nt < 4; nt++)
            #pragma unroll
            for (int e = 0; e < 4; e++) acc[mt][nt][e] = 0.f;

    uint4 bh0 = *(const uint4*)(pW1h), bh1 = *(const uint4*)(pW1h + 4);
    uint4 bl0 = *(const uint4*)(pW1l), bl1 = *(const uint4*)(pW1l + 4);

    // ================= GEMM1: pre = inter @ W1 (M=64, N=256, K=128), bf16x3 =================
    #pragma unroll 1
    for (int ks = 0; ks < 8; ks++) {
        const unsigned* nh = (ks < 7) ? (pW1h + (ks + 1) * 2048) : pW2h;
        const unsigned* nl = (ks < 7) ? (pW1l + (ks + 1) * 2048) : pW2l;
        uint4 nh0 = *(const uint4*)(nh), nh1 = *(const uint4*)(nh + 4);
        uint4 nl0 = *(const uint4*)(nl), nl1 = *(const uint4*)(nl + 4);
        const unsigned Bh[4][2] = {{bh0.x, bh0.y}, {bh0.z, bh0.w}, {bh1.x, bh1.y}, {bh1.z, bh1.w}};
        const unsigned Bl[4][2] = {{bl0.x, bl0.y}, {bl0.z, bl0.w}, {bl1.x, bl1.y}, {bl1.z, bl1.w}};
        #pragma unroll
        for (int mt = 0; mt < 4; mt++) {
            unsigned ahi[4], alo[4];
            ldm4(ahi, aHiB + (uint32_t)((mt * 8 + ks) * 512));
            ldm4(alo, aLoB + (uint32_t)((mt * 8 + ks) * 512));
            #pragma unroll
            for (int nt = 0; nt < 4; nt++) {
                mma4(acc[mt][nt], ahi, Bh[nt][0], Bh[nt][1]);
                mma4(acc[mt][nt], ahi, Bl[nt][0], Bl[nt][1]);
                mma4(acc[mt][nt], alo, Bh[nt][0], Bh[nt][1]);
            }
        }
        bh0 = nh0; bh1 = nh1; bl0 = nl0; bl1 = nl1;
    }
    __syncthreads();  // all inter reads complete before h overwrites the tile region

    // ---- tanh + split + store h tiles ----
    #pragma unroll
    for (int mt = 0; mt < 4; mt++) {
        #pragma unroll
        for (int nt = 0; nt < 4; nt++) {
            const int e = nt & 1;
            const uint32_t tb = (uint32_t)((mt * 16 + 2 * w + (nt >> 1)) * 512);
            const int inrow = 16 * e + 4 * q;
            unsigned lo;
            unsigned hi = pk(tanhf(acc[mt][nt][0]), tanhf(acc[mt][nt][1]), lo);
            uint32_t o = (uint32_t)((r * 32 + inrow) ^ ((r & 4) << 2));
            sts32(su + OFF_AHI + tb + o, hi);
            sts32(su + OFF_ALO + tb + o, lo);
            hi = pk(tanhf(acc[mt][nt][2]), tanhf(acc[mt][nt][3]), lo);
            const int r1 = r + 8;
            o = (uint32_t)((r1 * 32 + inrow) ^ ((r1 & 4) << 2));
            sts32(su + OFF_AHI + tb + o, hi);
            sts32(su + OFF_ALO + tb + o, lo);
        }
    }
    #pragma unroll
    for (int mt = 0; mt < 4; mt++)
        #pragma unroll
        for (int nt = 0; nt < 4; nt++)
            #pragma unroll
            for (int e = 0; e < 4; e++) acc[mt][nt][e] = 0.f;
    __syncthreads();

    // ================= GEMM2 (M=64, N=2048 flattened: 128 t-steps, epilogue every 16) ========
    #pragma unroll 1
    for (int t = 0; t < 128; t++) {
        const int tn = (t < 127) ? (t + 1) : 0;
        const unsigned* nh = pW2h + tn * 2048;
        const unsigned* nl = pW2l + tn * 2048;
        uint4 nh0 = *(const uint4*)(nh), nh1 = *(const uint4*)(nh + 4);
        uint4 nl0 = *(const uint4*)(nl), nl1 = *(const uint4*)(nl + 4);
        const unsigned Bh[4][2] = {{bh0.x, bh0.y}, {bh0.z, bh0.w}, {bh1.x, bh1.y}, {bh1.z, bh1.w}};
        const unsigned Bl[4][2] = {{bl0.x, bl0.y}, {bl0.z, bl0.w}, {bl1.x, bl1.y}, {bl1.z, bl1.w}};
        const int kc = t & 15;
        #pragma unroll
        for (int mt = 0; mt < 4; mt++) {
            unsigned ahi[4], alo[4];
            ldm4(ahi, aHiB + (uint32_t)((mt * 16 + kc) * 512));
            ldm4(alo, aLoB + (uint32_t)((mt * 16 + kc) * 512));
            #pragma unroll
            for (int nt = 0; nt < 4; nt++) {
                mma4(acc[mt][nt], ahi, Bh[nt][0], Bh[nt][1]);
                mma4(acc[mt][nt], ahi, Bl[nt][0], Bl[nt][1]);
                mma4(acc[mt][nt], alo, Bh[nt][0], Bh[nt][1]);
            }
        }
        bh0 = nh0; bh1 = nh1; bl0 = nl0; bl1 = nl1;

        if (kc == 15) {
            const int pass = t >> 4;
            // epilogue: out[m][c] = sum_b H[m][16c+b]*basis[m][b]
            #pragma unroll
            for (int mt = 0; mt < 4; mt++) {
                const int row0 = mt * 16 + r, row1 = row0 + 8;
                float b00 = sBas[row0 * 17 + 2 * q],     b01 = sBas[row0 * 17 + 2 * q + 1];
                float b08 = sBas[row0 * 17 + 8 + 2 * q], b09 = sBas[row0 * 17 + 9 + 2 * q];
                float b10 = sBas[row1 * 17 + 2 * q],     b11 = sBas[row1 * 17 + 2 * q + 1];
                float b18 = sBas[row1 * 17 + 8 + 2 * q], b19 = sBas[row1 * 17 + 9 + 2 * q];
                #pragma unroll
                for (int tp = 0; tp < 2; tp++) {
                    float s0 = acc[mt][2 * tp][0] * b00 + acc[mt][2 * tp][1] * b01
                             + acc[mt][2 * tp + 1][0] * b08 + acc[mt][2 * tp + 1][1] * b09;
                    float s1 = acc[mt][2 * tp][2] * b10 + acc[mt][2 * tp][3] * b11
                             + acc[mt][2 * tp + 1][2] * b18 + acc[mt][2 * tp + 1][3] * b19;
                    s0 += __shfl_xor_sync(0xffffffffu, s0, 1);
                    s0 += __shfl_xor_sync(0xffffffffu, s0, 2);
                    s1 += __shfl_xor_sync(0xffffffffu, s1, 1);
                    s1 += __shfl_xor_sync(0xffffffffu, s1, 2);
                    if (q == 0) {
                        const int c = pass * 16 + w * 2 + tp;
                        sOut[row0 * 132 + c] = s0;
                        sOut[row1 * 132 + c] = s1;
                    }
                }
                #pragma unroll
                for (int nt = 0; nt < 4; nt++)
                    #pragma unroll
                    for (int e = 0; e < 4; e++) acc[mt][nt][e] = 0.f;
            }
        }
    }
    __syncthreads();

    // ---- coalesced output store ----
    #pragma unroll 1
    for (int i = tid; i < TM * 32; i += 256) {
        const int m = i >> 5, c4 = i & 31;
        if (m < mvalid) {
            const float4 v = *(const float4*)(sOut + m * 132 + c4 * 4);
            *(float4*)(out + ((size_t)(m0 + m)) * NIN + c4 * 4) = v;
        }
    }
}

extern "C" void kernel_launch(void* const* d_in, const int* in_sizes, int n_in,
                              void* d_out, int out_size) {
    const float* prop  = (const float*)d_in[0];
    const void*  idxi  = d_in[1];
    const void*  idxj  = d_in[2];
    const float* basis = (const float*)d_in[3];
    const float* W1    = (const float*)d_in[4];
    const float* W2    = (const float*)d_in[5];
    float* out = (float*)d_out;
    const int P = out_size / NIN;
    (void)in_sizes; (void)n_in;

    cudaFuncSetAttribute(pilayer_kernel, cudaFuncAttributeMaxDynamicSharedMemorySize, SMEM_BYTES);

    detect_idx_kernel<<<1, 32>>>((const unsigned*)idxi);
    prep_w1_kernel<<<64, 256>>>(W1);
    prep_w2_kernel<<<1024, 256>>>(W2);

    const int blocks = (P + TM - 1) / TM;
    pilayer_kernel<<<blocks, 256, SMEM_BYTES>>>(prop, idxi, idxj, basis, out, P);
}